// round 8
// baseline (speedup 1.0000x reference)
#include <cuda_runtime.h>

// Problem constants
#define B_    2048
#define T_    512
#define FIN_  32
#define H_    64
#define G4_   256        // 4*H
#define HOR_  48
#define FOUT_ 8
#define NROW  14         // batch rows per CTA
#define NCTA  147        // ceil(2048/14)
#define RTHREADS 512

typedef unsigned long long u64;

// ---------------- scratch (__device__ globals; no cudaMalloc allowed) ----------------
__device__ float d_g0[(size_t)T_ * B_ * G4_];   // precomputed x-part of enc layer0 gates [t][b][256]
__device__ float d_WcT[FIN_ * G4_];             // combined (Wih0 @ W_emb) transposed [f][g]
__device__ float d_bc[G4_];                     // combined layer0 bias
__device__ float d_wih0P[H_ * G4_];             // decoder Wih[0], packed [k2][gp][4]

// ---------------- fast activations ----------------
__device__ __forceinline__ float sigf(float x) {
    return __fdividef(1.0f, 1.0f + __expf(-x));
}
__device__ __forceinline__ float tanh_f(float x) {
    return __fdividef(2.0f, 1.0f + __expf(-2.0f * x)) - 1.0f;
}

// ---------------- packed fp32x2 helpers ----------------
__device__ __forceinline__ u64 fma2(u64 a, u64 b, u64 c) {
    u64 d;
    asm("fma.rn.f32x2 %0, %1, %2, %3;" : "=l"(d) : "l"(a), "l"(b), "l"(c));
    return d;
}
__device__ __forceinline__ u64 add2(u64 a, u64 b) {
    u64 d;
    asm("add.rn.f32x2 %0, %1, %2;" : "=l"(d) : "l"(a), "l"(b));
    return d;
}
__device__ __forceinline__ float hadd2(u64 a) {
    float lo, hi;
    asm("mov.b64 {%0, %1}, %2;" : "=f"(lo), "=f"(hi) : "l"(a));
    return lo + hi;
}
// reduce across the 4 k-split lanes (low 2 bits of lane id)
__device__ __forceinline__ u64 red4(u64 a) {
    a = add2(a, __shfl_xor_sync(0xffffffffu, a, 1));
    a = add2(a, __shfl_xor_sync(0xffffffffu, a, 2));
    return a;
}

// weight packing: dst float index for gmem W[g*64+k]
__device__ __forceinline__ int wpack(int g, int k) {
    return (k >> 1) * 512 + (g >> 1) * 4 + (g & 1) * 2 + (k & 1);
}

// ---------------- prep: combined weights / packed transposes ----------------
__global__ void prep_kernel(const float* __restrict__ W_emb, const float* __restrict__ b_emb,
                            const float* __restrict__ encWih, const float* __restrict__ encbih,
                            const float* __restrict__ encbhh, const float* __restrict__ decWih)
{
    int g  = threadIdx.x;   // 0..255
    int bb = blockIdx.x;    // 0..32
    float wrow[H_];
#pragma unroll
    for (int h = 0; h < H_; h++) wrow[h] = encWih[g * H_ + h];

    if (bb == FIN_) {
        float b = encbih[g] + encbhh[g];
#pragma unroll
        for (int h = 0; h < H_; h++) b = fmaf(wrow[h], b_emb[h], b);
        d_bc[g] = b;
#pragma unroll
        for (int k = 0; k < H_; k++)
            d_wih0P[wpack(g, k)] = decWih[g * H_ + k];
    } else {
        int f = bb;
        float s = 0.f;
#pragma unroll
        for (int h = 0; h < H_; h++) s = fmaf(wrow[h], W_emb[h * FIN_ + f], s);
        d_WcT[f * G4_ + g] = s;
    }
}

// ---------------- GEMM: d_g0[t][b][g] = X[b][t][:] @ WcT + bc ----------------
__global__ void __launch_bounds__(256)
emb_gemm(const float* __restrict__ X)
{
    __shared__ float sX[128 * FIN_];
    const int t   = blockIdx.y;
    const int b0  = blockIdx.x * 128;
    const int tid = threadIdx.x;

#pragma unroll
    for (int q = 0; q < 4; q++) {
        int lin = tid + q * 256;
        int rr = lin >> 3, f4 = lin & 7;
        float4 v = *(const float4*)(X + ((size_t)(b0 + rr) * T_ + t) * FIN_ + f4 * 4);
        *(float4*)(sX + rr * FIN_ + f4 * 4) = v;
    }
    float w[FIN_];
#pragma unroll
    for (int f = 0; f < FIN_; f++) w[f] = d_WcT[f * G4_ + tid];
    const float bias = d_bc[tid];
    __syncthreads();

    float* dst = d_g0 + (size_t)t * B_ * G4_ + (size_t)b0 * G4_ + tid;
#pragma unroll 2
    for (int rr = 0; rr < 128; rr++) {
        float a = bias;
        const float* xr = sX + rr * FIN_;
#pragma unroll
        for (int f = 0; f < FIN_; f += 4) {
            float4 x = *(const float4*)(xr + f);
            a = fmaf(x.x, w[f + 0], a);
            a = fmaf(x.y, w[f + 1], a);
            a = fmaf(x.z, w[f + 2], a);
            a = fmaf(x.w, w[f + 3], a);
        }
        dst[(size_t)rr * G4_] = a;
    }
}

// ---------------- matvec accumulate: 7 rows, thread's k-range (16), 2 gates ----------------
__device__ __forceinline__ void mv_acc(u64 acc0[7], u64 acc1[7],
                                       const float* __restrict__ hb,   // 7 rows x 64
                                       const float* __restrict__ wS,   // packed matrix (smem)
                                       int gp, int ks)
{
#pragma unroll
    for (int j = 0; j < 4; j++) {
        int k2 = ks * 8 + j * 2;
        const float* wp = wS + k2 * 512 + gp * 4;
        ulonglong2 wa = *(const ulonglong2*)(wp);         // k2:   (g0 pair, g1 pair)
        ulonglong2 wb = *(const ulonglong2*)(wp + 512);   // k2+1
        int k0 = ks * 16 + j * 4;
#pragma unroll
        for (int r = 0; r < 7; r++) {
            ulonglong2 h = *(const ulonglong2*)(hb + r * 64 + k0);
            acc0[r] = fma2(h.x, wa.x, acc0[r]);
            acc1[r] = fma2(h.x, wa.y, acc1[r]);
            acc0[r] = fma2(h.y, wb.x, acc0[r]);
            acc1[r] = fma2(h.y, wb.y, acc1[r]);
        }
    }
}

// same, packed weights streamed from global (decoder dWih0, L2-resident)
__device__ __forceinline__ void mv_acc_g(u64 acc0[7], u64 acc1[7],
                                         const float* __restrict__ hb,
                                         const float* __restrict__ wG,
                                         int gp, int ks)
{
#pragma unroll
    for (int j = 0; j < 4; j++) {
        int k2 = ks * 8 + j * 2;
        const float* wp = wG + k2 * 512 + gp * 4;
        ulonglong2 wa = __ldg((const ulonglong2*)(wp));
        ulonglong2 wb = __ldg((const ulonglong2*)(wp + 512));
        int k0 = ks * 16 + j * 4;
#pragma unroll
        for (int r = 0; r < 7; r++) {
            ulonglong2 h = *(const ulonglong2*)(hb + r * 64 + k0);
            acc0[r] = fma2(h.x, wa.x, acc0[r]);
            acc1[r] = fma2(h.x, wa.y, acc1[r]);
            acc0[r] = fma2(h.y, wb.x, acc0[r]);
            acc1[r] = fma2(h.y, wb.y, acc1[r]);
        }
    }
}

// reduce across 4 k-split lanes; lane ks stores rows {r : r&3==ks} with add value
__device__ __forceinline__ void reduce_store(u64 acc0[7], u64 acc1[7],
                                             float* __restrict__ sGrow,  // sG + batchbase*256 + 2*gp
                                             int ks, float2 add0, float2 add1)
{
#pragma unroll
    for (int r = 0; r < 7; r++) {
        u64 a0 = red4(acc0[r]);
        u64 a1 = red4(acc1[r]);
        if ((r & 3) == ks) {
            float2 ad = (r < 4) ? add0 : add1;
            float2 v;
            v.x = hadd2(a0) + ad.x;
            v.y = hadd2(a1) + ad.y;
            *(float2*)(sGrow + r * G4_) = v;
        }
    }
}

// pointwise LSTM update for one element; c lives in a register
__device__ __forceinline__ void upd_elem(const float* __restrict__ sG,
                                         float* __restrict__ sHL, float& c, int e)
{
    int r = e >> 6, jj = e & 63;
    const float* gr = sG + r * G4_;
    float gi = gr[jj];
    float gf = gr[64 + jj];
    float gc = gr[128 + jj];
    float go = gr[192 + jj];
    float cn = sigf(gf) * c + sigf(gi) * tanh_f(gc);
    c = cn;
    sHL[r * 64 + jj] = sigf(go) * tanh_f(cn);
}

// smem: sW 3*16384 | sH 2*896 | sG 3584 | sB 512 | sWr 512 | sBr 8
#define SMEM_FLOATS (3*16384 + 2*896 + 3584 + 512 + 512 + 8)
#define SMEM_BYTES  (SMEM_FLOATS * 4)

__global__ void __launch_bounds__(RTHREADS, 1)
rnn_kernel(const float* __restrict__ encWih, const float* __restrict__ encWhh,
           const float* __restrict__ encbih, const float* __restrict__ encbhh,
           const float* __restrict__ decWih, const float* __restrict__ decWhh,
           const float* __restrict__ decbih, const float* __restrict__ decbhh,
           const float* __restrict__ Wreg,   const float* __restrict__ breg,
           float* __restrict__ out)
{
    extern __shared__ float sm[];
    float* sW  = sm;                 // 3 packed matrices
    float* sH  = sW + 3 * 16384;     // [layer][14][64]
    float* sG  = sH + 2 * 896;       // [14][256]
    float* sB  = sG + 3584;          // [2][256] biases
    float* sWr = sB + 512;
    float* sBr = sWr + FOUT_ * H_;

    const int tid = threadIdx.x;
    const int gp  = tid >> 2;        // gate pair 0..127 (gates 2gp, 2gp+1)
    const int ks  = tid & 3;         // k-split 0..3 (k in [16ks,16ks+16))
    const int b0  = blockIdx.x * NROW;
    const int nrows = (B_ - b0 < NROW) ? (B_ - b0) : NROW;

    float* sH0 = sH;
    float* sH1 = sH + 896;

    // pack encoder weights: slot0=encWhh[0], slot1=encWih[1], slot2=encWhh[1]
    for (int i = tid; i < 16384; i += RTHREADS) {
        int g = i >> 6, k = i & 63;
        int dst = wpack(g, k);
        sW[dst]          = encWhh[i];
        sW[16384 + dst]  = encWih[16384 + i];
        sW[32768 + dst]  = encWhh[16384 + i];
    }
    for (int i = tid; i < G4_; i += RTHREADS)
        sB[256 + i] = encbih[256 + i] + encbhh[256 + i];
    for (int i = tid; i < 2 * 896; i += RTHREADS) sH[i] = 0.f;
    __syncthreads();

    const float2 b1 = *(const float2*)(sB + 256 + 2 * gp);

    // store-row assignment and x-part prefetch offsets
    const int rA0 = ks, rA1 = ks + 4;        // batch0 (rA1 valid iff ks<3)
    const int rB0 = 7 + ks, rB1 = 11 + ks;   // batch1 (rB1 valid iff ks<3)
    #define BCLAMP(r) ((b0 + (r) < B_) ? (b0 + (r)) : (B_ - 1))
    const size_t offA0 = (size_t)BCLAMP(rA0) * G4_ + 2 * gp;
    const size_t offA1 = (size_t)BCLAMP(rA1) * G4_ + 2 * gp;
    const size_t offB0 = (size_t)BCLAMP(rB0) * G4_ + 2 * gp;
    const size_t offB1 = (size_t)BCLAMP(rB1) * G4_ + 2 * gp;

    float2 gxA0, gxA1, gxB0, gxB1;
    gxA0 = *(const float2*)(d_g0 + offA0);
    gxA1 = (ks < 3) ? *(const float2*)(d_g0 + offA1) : make_float2(0.f, 0.f);
    gxB0 = *(const float2*)(d_g0 + offB0);
    gxB1 = (ks < 3) ? *(const float2*)(d_g0 + offB1) : make_float2(0.f, 0.f);

    // update-phase elements; cells live in registers
    const int e0 = tid, e1 = tid + 512;
    const bool has_e1 = (e1 < 2 * 448);      // 896 elements per layer
    float c00 = 0.f, c01 = 0.f, c10 = 0.f, c11 = 0.f;

    // -------------------- encoder: 512 steps --------------------
    for (int t = 0; t < T_; t++) {
        u64 a0[7], a1[7];
        // ---- layer 0 ----
#pragma unroll
        for (int r = 0; r < 7; r++) { a0[r] = 0ull; a1[r] = 0ull; }
        mv_acc(a0, a1, sH0, sW, gp, ks);
        reduce_store(a0, a1, sG + 2 * gp, ks, gxA0, gxA1);
#pragma unroll
        for (int r = 0; r < 7; r++) { a0[r] = 0ull; a1[r] = 0ull; }
        mv_acc(a0, a1, sH0 + 7 * 64, sW, gp, ks);
        reduce_store(a0, a1, sG + 7 * G4_ + 2 * gp, ks, gxB0, gxB1);
        // prefetch x-part for t+1
        if (t + 1 < T_) {
            const float* p = d_g0 + (size_t)(t + 1) * B_ * G4_;
            gxA0 = *(const float2*)(p + offA0);
            if (ks < 3) gxA1 = *(const float2*)(p + offA1);
            gxB0 = *(const float2*)(p + offB0);
            if (ks < 3) gxB1 = *(const float2*)(p + offB1);
        }
        __syncthreads();
        upd_elem(sG, sH0, c00, e0);
        if (has_e1) upd_elem(sG, sH0, c01, e1);
        __syncthreads();
        // ---- layer 1 ----
#pragma unroll
        for (int r = 0; r < 7; r++) { a0[r] = 0ull; a1[r] = 0ull; }
        mv_acc(a0, a1, sH0, sW + 16384, gp, ks);
        mv_acc(a0, a1, sH1, sW + 32768, gp, ks);
        reduce_store(a0, a1, sG + 2 * gp, ks, b1, b1);
#pragma unroll
        for (int r = 0; r < 7; r++) { a0[r] = 0ull; a1[r] = 0ull; }
        mv_acc(a0, a1, sH0 + 7 * 64, sW + 16384, gp, ks);
        mv_acc(a0, a1, sH1 + 7 * 64, sW + 32768, gp, ks);
        reduce_store(a0, a1, sG + 7 * G4_ + 2 * gp, ks, b1, b1);
        __syncthreads();
        upd_elem(sG, sH1, c10, e0);
        if (has_e1) upd_elem(sG, sH1, c11, e1);
        __syncthreads();
    }

    // -------------------- decoder setup --------------------
    for (int i = tid; i < 16384; i += RTHREADS) {
        int g = i >> 6, k = i & 63;
        int dst = wpack(g, k);
        sW[dst]          = decWhh[i];             // dWhh0
        sW[16384 + dst]  = decWih[16384 + i];     // dWih1
        sW[32768 + dst]  = decWhh[16384 + i];     // dWhh1
    }
    for (int i = tid; i < G4_; i += RTHREADS) {
        sB[i]       = decbih[i] + decbhh[i];
        sB[256 + i] = decbih[256 + i] + decbhh[256 + i];
    }
    for (int i = tid; i < FOUT_ * H_; i += RTHREADS) sWr[i] = Wreg[i];
    if (tid < FOUT_) sBr[tid] = breg[tid];
    c00 = c01 = c10 = c11 = 0.f;      // c reset; h carries over
    __syncthreads();

    const float2 db0 = *(const float2*)(sB + 2 * gp);
    const float2 db1 = *(const float2*)(sB + 256 + 2 * gp);

    // -------------------- decoder: 48 steps --------------------
    for (int t = 0; t < HOR_; t++) {
        u64 a0[7], a1[7];
        // ---- layer 0: input = h1_prev (dWih0 from gmem) + h0 @ dWhh0 ----
#pragma unroll
        for (int r = 0; r < 7; r++) { a0[r] = 0ull; a1[r] = 0ull; }
        mv_acc_g(a0, a1, sH1, d_wih0P, gp, ks);
        mv_acc(a0, a1, sH0, sW, gp, ks);
        reduce_store(a0, a1, sG + 2 * gp, ks, db0, db0);
#pragma unroll
        for (int r = 0; r < 7; r++) { a0[r] = 0ull; a1[r] = 0ull; }
        mv_acc_g(a0, a1, sH1 + 7 * 64, d_wih0P, gp, ks);
        mv_acc(a0, a1, sH0 + 7 * 64, sW, gp, ks);
        reduce_store(a0, a1, sG + 7 * G4_ + 2 * gp, ks, db0, db0);
        __syncthreads();
        upd_elem(sG, sH0, c00, e0);
        if (has_e1) upd_elem(sG, sH0, c01, e1);
        __syncthreads();
        // ---- layer 1 ----
#pragma unroll
        for (int r = 0; r < 7; r++) { a0[r] = 0ull; a1[r] = 0ull; }
        mv_acc(a0, a1, sH0, sW + 16384, gp, ks);
        mv_acc(a0, a1, sH1, sW + 32768, gp, ks);
        reduce_store(a0, a1, sG + 2 * gp, ks, db1, db1);
#pragma unroll
        for (int r = 0; r < 7; r++) { a0[r] = 0ull; a1[r] = 0ull; }
        mv_acc(a0, a1, sH0 + 7 * 64, sW + 16384, gp, ks);
        mv_acc(a0, a1, sH1 + 7 * 64, sW + 32768, gp, ks);
        reduce_store(a0, a1, sG + 7 * G4_ + 2 * gp, ks, db1, db1);
        __syncthreads();
        upd_elem(sG, sH1, c10, e0);
        if (has_e1) upd_elem(sG, sH1, c11, e1);
        __syncthreads();
        // regression head: y = h1_new @ Wreg^T + breg
        if (tid < NROW * FOUT_) {
            int r = tid >> 3, o = tid & 7;
            if (r < nrows) {
                float a = sBr[o];
                const float* hr = sH1 + r * 64;
#pragma unroll
                for (int k = 0; k < H_; k += 4) {
                    float4 h4 = *(const float4*)(hr + k);
                    float4 w4 = *(const float4*)(sWr + o * H_ + k);
                    a = fmaf(h4.x, w4.x, a);
                    a = fmaf(h4.y, w4.y, a);
                    a = fmaf(h4.z, w4.z, a);
                    a = fmaf(h4.w, w4.w, a);
                }
                out[((size_t)(b0 + r) * HOR_ + t) * FOUT_ + o] = a;
            }
        }
    }
}

// ---------------- launch ----------------
extern "C" void kernel_launch(void* const* d_in, const int* in_sizes, int n_in,
                              void* d_out, int out_size)
{
    const float* X      = (const float*)d_in[0];
    // d_in[1] = X_mask : all-ones, unused by reference
    const float* W_emb  = (const float*)d_in[2];
    const float* b_emb  = (const float*)d_in[3];
    const float* encWih = (const float*)d_in[4];
    const float* encWhh = (const float*)d_in[5];
    const float* encbih = (const float*)d_in[6];
    const float* encbhh = (const float*)d_in[7];
    const float* decWih = (const float*)d_in[8];
    const float* decWhh = (const float*)d_in[9];
    const float* decbih = (const float*)d_in[10];
    const float* decbhh = (const float*)d_in[11];
    const float* W_reg  = (const float*)d_in[12];
    const float* b_reg  = (const float*)d_in[13];
    float* out = (float*)d_out;

    cudaFuncSetAttribute(rnn_kernel, cudaFuncAttributeMaxDynamicSharedMemorySize, SMEM_BYTES);

    prep_kernel<<<FIN_ + 1, 256>>>(W_emb, b_emb, encWih, encbih, encbhh, decWih);
    emb_gemm<<<dim3(B_ / 128, T_), 256>>>(X);
    rnn_kernel<<<NCTA, RTHREADS, SMEM_BYTES>>>(encWih, encWhh, encbih, encbhh,
                                               decWih, decWhh, decbih, decbhh,
                                               W_reg, b_reg, out);
}

// round 9
// speedup vs baseline: 3.2083x; 3.2083x over previous
#include <cuda_runtime.h>

// Problem constants
#define B_    2048
#define T_    512
#define FIN_  32
#define H_    64
#define G4_   256        // 4*H
#define HOR_  48
#define FOUT_ 8
#define NROW  14         // batch rows per CTA
#define NCTA  147        // ceil(2048/14)
#define RTHREADS 512
#define G0ROW (B_ * G4_)

typedef unsigned long long u64;

// ---------------- scratch (__device__ globals; no cudaMalloc allowed) ----------------
__device__ float d_g0[(size_t)T_ * B_ * G4_];   // x-part of enc layer0 gates [t][b][256]
__device__ float d_WcT[FIN_ * G4_];             // combined (Wih0 @ W_emb) transposed [f][g]
__device__ float d_bc[G4_];                     // combined layer0 bias
__device__ float d_wih0P[H_ * G4_];             // decoder Wih[0], packed wpk layout

// ---------------- fast activations ----------------
__device__ __forceinline__ float sigf(float x) {
    return __fdividef(1.0f, 1.0f + __expf(-x));
}
__device__ __forceinline__ float tanh_f(float x) {
    return __fdividef(2.0f, 1.0f + __expf(-2.0f * x)) - 1.0f;
}

// ---------------- packed fp32x2 helpers ----------------
__device__ __forceinline__ u64 fma2(u64 a, u64 b, u64 c) {
    u64 d;
    asm("fma.rn.f32x2 %0, %1, %2, %3;" : "=l"(d) : "l"(a), "l"(b), "l"(c));
    return d;
}
__device__ __forceinline__ float hadd2(u64 a) {
    float lo, hi;
    asm("mov.b64 {%0, %1}, %2;" : "=f"(lo), "=f"(hi) : "l"(a));
    return lo + hi;
}

// per-row-half named barrier: rh 0 -> id 1 (warps 0-7), rh 1 -> id 2 (warps 8-15)
__device__ __forceinline__ void barh(int rh) {
    asm volatile("bar.sync %0, 256;" :: "r"(rh + 1) : "memory");
}

// weight packing: for element W[g][k] of a 256x64 matrix.
// Layout: [kh][kq][ab][gp][4] where kh=k>>5, kq=(k>>2)&7, ab=(k>>1)&1,
// inner 4 floats = {g0 k_even, g0 k_odd, g1 k_even, g1 k_odd}
__device__ __forceinline__ int wpk(int g, int k) {
    return ((k >> 5) << 13) + ((((k >> 2) & 7) << 1) + ((k >> 1) & 1)) * 512
         + ((g >> 1) << 2) + ((g & 1) << 1) + (k & 1);
}

// ---------------- prep: combined weights / packed transposes ----------------
__global__ void prep_kernel(const float* __restrict__ W_emb, const float* __restrict__ b_emb,
                            const float* __restrict__ encWih, const float* __restrict__ encbih,
                            const float* __restrict__ encbhh, const float* __restrict__ decWih)
{
    int g  = threadIdx.x;   // 0..255
    int bb = blockIdx.x;    // 0..32
    float wrow[H_];
#pragma unroll
    for (int h = 0; h < H_; h++) wrow[h] = encWih[g * H_ + h];

    if (bb == FIN_) {
        float b = encbih[g] + encbhh[g];
#pragma unroll
        for (int h = 0; h < H_; h++) b = fmaf(wrow[h], b_emb[h], b);
        d_bc[g] = b;
#pragma unroll
        for (int k = 0; k < H_; k++)
            d_wih0P[wpk(g, k)] = decWih[g * H_ + k];
    } else {
        int f = bb;
        float s = 0.f;
#pragma unroll
        for (int h = 0; h < H_; h++) s = fmaf(wrow[h], W_emb[h * FIN_ + f], s);
        d_WcT[f * G4_ + g] = s;
    }
}

// ---------------- GEMM: d_g0[t][b][g] = X[b][t][:] @ WcT + bc ----------------
__global__ void __launch_bounds__(256)
emb_gemm(const float* __restrict__ X)
{
    __shared__ float sX[128 * FIN_];
    const int t   = blockIdx.y;
    const int b0  = blockIdx.x * 128;
    const int tid = threadIdx.x;

#pragma unroll
    for (int q = 0; q < 4; q++) {
        int lin = tid + q * 256;
        int rr = lin >> 3, f4 = lin & 7;
        float4 v = *(const float4*)(X + ((size_t)(b0 + rr) * T_ + t) * FIN_ + f4 * 4);
        *(float4*)(sX + rr * FIN_ + f4 * 4) = v;
    }
    float w[FIN_];
#pragma unroll
    for (int f = 0; f < FIN_; f++) w[f] = d_WcT[f * G4_ + tid];
    const float bias = d_bc[tid];
    __syncthreads();

    float* dst = d_g0 + (size_t)t * B_ * G4_ + (size_t)b0 * G4_ + tid;
#pragma unroll 2
    for (int rr = 0; rr < 128; rr++) {
        float a = bias;
        const float* xr = sX + rr * FIN_;
#pragma unroll
        for (int f = 0; f < FIN_; f += 4) {
            float4 x = *(const float4*)(xr + f);
            a = fmaf(x.x, w[f + 0], a);
            a = fmaf(x.y, w[f + 1], a);
            a = fmaf(x.z, w[f + 2], a);
            a = fmaf(x.w, w[f + 3], a);
        }
        dst[(size_t)rr * G4_] = a;
    }
}

// ---------------- partial matvec: 7 rows x this thread's k-half (32) x 2 gates ----------------
// hb  = sH + layer*896 + rbase*64 + kh*32  (row-half + k-half base)
// wKH = matrix base + kh*8192 (packed wpk layout)
__device__ __forceinline__ void mv_p(u64 acc[7][2], const float* __restrict__ hb,
                                     const float* __restrict__ wKH, int gp)
{
#pragma unroll
    for (int kq = 0; kq < 8; kq++) {
        const float* wp = wKH + kq * 1024 + gp * 4;
        ulonglong2 wa = *(const ulonglong2*)(wp);         // (g0 pair, g1 pair) for k = base+{0,1}
        ulonglong2 wb = *(const ulonglong2*)(wp + 512);   // for k = base+{2,3}
        const float* hq = hb + kq * 4;
#pragma unroll
        for (int r = 0; r < 7; r++) {
            ulonglong2 h = *(const ulonglong2*)(hq + r * 64);
            acc[r][0] = fma2(h.x, wa.x, acc[r][0]);
            acc[r][1] = fma2(h.x, wa.y, acc[r][1]);
            acc[r][0] = fma2(h.y, wb.x, acc[r][0]);
            acc[r][1] = fma2(h.y, wb.y, acc[r][1]);
        }
    }
}

// same, packed weights streamed from global (decoder dWih0, L2-resident)
__device__ __forceinline__ void mv_pg(u64 acc[7][2], const float* __restrict__ hb,
                                      const float* __restrict__ wKH, int gp)
{
#pragma unroll
    for (int kq = 0; kq < 8; kq++) {
        const float* wp = wKH + kq * 1024 + gp * 4;
        ulonglong2 wa = __ldg((const ulonglong2*)(wp));
        ulonglong2 wb = __ldg((const ulonglong2*)(wp + 512));
        const float* hq = hb + kq * 4;
#pragma unroll
        for (int r = 0; r < 7; r++) {
            ulonglong2 h = *(const ulonglong2*)(hq + r * 64);
            acc[r][0] = fma2(h.x, wa.x, acc[r][0]);
            acc[r][1] = fma2(h.x, wa.y, acc[r][1]);
            acc[r][0] = fma2(h.y, wb.x, acc[r][0]);
            acc[r][1] = fma2(h.y, wb.y, acc[r][1]);
        }
    }
}

// pointwise LSTM update over this row-half (256 threads, 448 elems); c in registers
__device__ __forceinline__ void upd2(const float* __restrict__ sG, float* __restrict__ sHL,
                                     float& ca, float& cb, int lt, int rbase)
{
    {
        int e = lt;                       // always < 448
        int r = e >> 6, j = e & 63;
        const float* gr = sG + (rbase + r) * G4_;
        float gi = gr[j], gf = gr[64 + j], gc = gr[128 + j], go = gr[192 + j];
        float cn = sigf(gf) * ca + sigf(gi) * tanh_f(gc);
        ca = cn;
        sHL[(rbase + r) * 64 + j] = sigf(go) * tanh_f(cn);
    }
    if (lt < 192) {
        int e = lt + 256;
        int r = e >> 6, j = e & 63;
        const float* gr = sG + (rbase + r) * G4_;
        float gi = gr[j], gf = gr[64 + j], gc = gr[128 + j], go = gr[192 + j];
        float cn = sigf(gf) * cb + sigf(gi) * tanh_f(gc);
        cb = cn;
        sHL[(rbase + r) * 64 + j] = sigf(go) * tanh_f(cn);
    }
}

// smem: sW 3*16384 | sH 2*896 | sG 3584 | sWr 512 | sBr 8  = 55048 floats = 220192 B
#define SMEM_FLOATS (3*16384 + 2*896 + 3584 + 512 + 8)
#define SMEM_BYTES  (SMEM_FLOATS * 4)

__global__ void __launch_bounds__(RTHREADS, 1)
rnn_kernel(const float* __restrict__ encWih, const float* __restrict__ encWhh,
           const float* __restrict__ encbih, const float* __restrict__ encbhh,
           const float* __restrict__ decWih, const float* __restrict__ decWhh,
           const float* __restrict__ decbih, const float* __restrict__ decbhh,
           const float* __restrict__ Wreg,   const float* __restrict__ breg,
           float* __restrict__ out)
{
    extern __shared__ float sm[];
    float* sW  = sm;                 // 3 packed matrices (wpk layout)
    float* sH  = sW + 49152;         // [layer][14][64]
    float* sG  = sH + 1792;          // [14][256] gates (partials then finals)
    float* sWr = sG + 3584;          // [8][64]
    float* sBr = sWr + 512;          // [8]

    const int tid   = threadIdx.x;
    const int gp    = tid & 127;          // gate pair (gates 2gp, 2gp+1)
    const int kh    = (tid >> 7) & 1;     // k-half
    const int rh    = tid >> 8;           // row-half
    const int rbase = rh * 7;
    const int lt    = tid & 255;          // lane within row-half
    const int b0    = blockIdx.x * NROW;

    // pack encoder weights: slot0=encWhh[0], slot1=encWih[1], slot2=encWhh[1]
    for (int i = tid; i < 16384; i += RTHREADS) {
        int g = i >> 6, k = i & 63;
        int dst = wpk(g, k);
        sW[dst]         = encWhh[i];
        sW[16384 + dst] = encWih[16384 + i];
        sW[32768 + dst] = encWhh[16384 + i];
    }
    for (int i = tid; i < 2 * 896; i += RTHREADS) sH[i] = 0.f;
    __syncthreads();

    // biases (registers, kh0 uses them at finalize)
    float2 b1 = make_float2(encbih[256 + 2 * gp] + encbhh[256 + 2 * gp],
                            encbih[257 + 2 * gp] + encbhh[257 + 2 * gp]);

    // x-part row offsets (clamped for tail CTA)
    int goff[7];
#pragma unroll
    for (int j = 0; j < 7; j++) {
        int b = b0 + rbase + j;
        if (b >= B_) b = B_ - 1;
        goff[j] = b * G4_ + 2 * gp;
    }
    float2 gx[7];
    if (kh == 0) {
#pragma unroll
        for (int j = 0; j < 7; j++) gx[j] = *(const float2*)(d_g0 + goff[j]);
    }

    const float* h0b = sH + rbase * 64 + kh * 32;          // layer0 h, this k-half
    const float* h1b = sH + 896 + rbase * 64 + kh * 32;    // layer1 h
    float c0a = 0.f, c0b = 0.f, c1a = 0.f, c1b = 0.f;

    // -------------------- encoder: 512 steps --------------------
    for (int t = 0; t < T_; t++) {
        u64 acc[7][2];
        // ---- layer 0: W0 x h0 (k-half partial) ----
#pragma unroll
        for (int r = 0; r < 7; r++) { acc[r][0] = 0ull; acc[r][1] = 0ull; }
        mv_p(acc, h0b, sW + kh * 8192, gp);
        if (kh) {
#pragma unroll
            for (int r = 0; r < 7; r++) {
                float2 v; v.x = hadd2(acc[r][0]); v.y = hadd2(acc[r][1]);
                *(float2*)(sG + (rbase + r) * G4_ + 2 * gp) = v;
            }
        }
        barh(rh);
        if (!kh) {
#pragma unroll
            for (int r = 0; r < 7; r++) {
                float2 p = *(const float2*)(sG + (rbase + r) * G4_ + 2 * gp);
                float2 v;
                v.x = hadd2(acc[r][0]) + p.x + gx[r].x;
                v.y = hadd2(acc[r][1]) + p.y + gx[r].y;
                *(float2*)(sG + (rbase + r) * G4_ + 2 * gp) = v;
            }
            if (t + 1 < T_) {   // prefetch x-part for t+1 (latency hidden across phases)
                const float* pn = d_g0 + (size_t)(t + 1) * G0ROW;
#pragma unroll
                for (int j = 0; j < 7; j++) gx[j] = *(const float2*)(pn + goff[j]);
            }
        }
        barh(rh);
        upd2(sG, sH, c0a, c0b, lt, rbase);
        barh(rh);
        // ---- layer 1: Wih1 x h0_new + Whh1 x h1 ----
#pragma unroll
        for (int r = 0; r < 7; r++) { acc[r][0] = 0ull; acc[r][1] = 0ull; }
        mv_p(acc, h0b, sW + 16384 + kh * 8192, gp);
        mv_p(acc, h1b, sW + 32768 + kh * 8192, gp);
        if (kh) {
#pragma unroll
            for (int r = 0; r < 7; r++) {
                float2 v; v.x = hadd2(acc[r][0]); v.y = hadd2(acc[r][1]);
                *(float2*)(sG + (rbase + r) * G4_ + 2 * gp) = v;
            }
        }
        barh(rh);
        if (!kh) {
#pragma unroll
            for (int r = 0; r < 7; r++) {
                float2 p = *(const float2*)(sG + (rbase + r) * G4_ + 2 * gp);
                float2 v;
                v.x = hadd2(acc[r][0]) + p.x + b1.x;
                v.y = hadd2(acc[r][1]) + p.y + b1.y;
                *(float2*)(sG + (rbase + r) * G4_ + 2 * gp) = v;
            }
        }
        barh(rh);
        upd2(sG, sH + 896, c1a, c1b, lt, rbase);
        barh(rh);
    }

    // -------------------- decoder setup (cross-half: full syncs) --------------------
    __syncthreads();
    for (int i = tid; i < 16384; i += RTHREADS) {
        int g = i >> 6, k = i & 63;
        int dst = wpk(g, k);
        sW[dst]         = decWhh[i];             // dWhh0
        sW[16384 + dst] = decWih[16384 + i];     // dWih1
        sW[32768 + dst] = decWhh[16384 + i];     // dWhh1
    }
    for (int i = tid; i < FOUT_ * H_; i += RTHREADS) sWr[i] = Wreg[i];
    if (tid < FOUT_) sBr[tid] = breg[tid];
    float2 db0 = make_float2(decbih[2 * gp] + decbhh[2 * gp],
                             decbih[2 * gp + 1] + decbhh[2 * gp + 1]);
    float2 db1 = make_float2(decbih[256 + 2 * gp] + decbhh[256 + 2 * gp],
                             decbih[257 + 2 * gp] + decbhh[257 + 2 * gp]);
    c0a = c0b = c1a = c1b = 0.f;                 // c reset; h carries over
    __syncthreads();

    // -------------------- decoder: 48 steps --------------------
    for (int t = 0; t < HOR_; t++) {
        u64 acc[7][2];
        // ---- layer 0: dWih0 x h1_prev (gmem weights) + dWhh0 x h0 ----
#pragma unroll
        for (int r = 0; r < 7; r++) { acc[r][0] = 0ull; acc[r][1] = 0ull; }
        mv_pg(acc, h1b, d_wih0P + kh * 8192, gp);
        mv_p (acc, h0b, sW + kh * 8192, gp);
        if (kh) {
#pragma unroll
            for (int r = 0; r < 7; r++) {
                float2 v; v.x = hadd2(acc[r][0]); v.y = hadd2(acc[r][1]);
                *(float2*)(sG + (rbase + r) * G4_ + 2 * gp) = v;
            }
        }
        barh(rh);
        if (!kh) {
#pragma unroll
            for (int r = 0; r < 7; r++) {
                float2 p = *(const float2*)(sG + (rbase + r) * G4_ + 2 * gp);
                float2 v;
                v.x = hadd2(acc[r][0]) + p.x + db0.x;
                v.y = hadd2(acc[r][1]) + p.y + db0.y;
                *(float2*)(sG + (rbase + r) * G4_ + 2 * gp) = v;
            }
        }
        barh(rh);
        upd2(sG, sH, c0a, c0b, lt, rbase);
        barh(rh);
        // ---- layer 1 ----
#pragma unroll
        for (int r = 0; r < 7; r++) { acc[r][0] = 0ull; acc[r][1] = 0ull; }
        mv_p(acc, h0b, sW + 16384 + kh * 8192, gp);
        mv_p(acc, h1b, sW + 32768 + kh * 8192, gp);
        if (kh) {
#pragma unroll
            for (int r = 0; r < 7; r++) {
                float2 v; v.x = hadd2(acc[r][0]); v.y = hadd2(acc[r][1]);
                *(float2*)(sG + (rbase + r) * G4_ + 2 * gp) = v;
            }
        }
        barh(rh);
        if (!kh) {
#pragma unroll
            for (int r = 0; r < 7; r++) {
                float2 p = *(const float2*)(sG + (rbase + r) * G4_ + 2 * gp);
                float2 v;
                v.x = hadd2(acc[r][0]) + p.x + db1.x;
                v.y = hadd2(acc[r][1]) + p.y + db1.y;
                *(float2*)(sG + (rbase + r) * G4_ + 2 * gp) = v;
            }
        }
        barh(rh);
        upd2(sG, sH + 896, c1a, c1b, lt, rbase);
        barh(rh);
        // regression head: y = h1_new @ Wreg^T + breg (row-half local)
        if (lt < 7 * FOUT_) {
            int rloc = lt >> 3, o = lt & 7;
            int b = b0 + rbase + rloc;
            if (b < B_) {
                float a = sBr[o];
                const float* hr = sH + 896 + (rbase + rloc) * 64;
#pragma unroll
                for (int k = 0; k < H_; k += 4) {
                    float4 h4 = *(const float4*)(hr + k);
                    float4 w4 = *(const float4*)(sWr + o * H_ + k);
                    a = fmaf(h4.x, w4.x, a);
                    a = fmaf(h4.y, w4.y, a);
                    a = fmaf(h4.z, w4.z, a);
                    a = fmaf(h4.w, w4.w, a);
                }
                out[((size_t)b * HOR_ + t) * FOUT_ + o] = a;
            }
        }
    }
}

// ---------------- launch ----------------
extern "C" void kernel_launch(void* const* d_in, const int* in_sizes, int n_in,
                              void* d_out, int out_size)
{
    const float* X      = (const float*)d_in[0];
    // d_in[1] = X_mask : all-ones, unused by reference
    const float* W_emb  = (const float*)d_in[2];
    const float* b_emb  = (const float*)d_in[3];
    const float* encWih = (const float*)d_in[4];
    const float* encWhh = (const float*)d_in[5];
    const float* encbih = (const float*)d_in[6];
    const float* encbhh = (const float*)d_in[7];
    const float* decWih = (const float*)d_in[8];
    const float* decWhh = (const float*)d_in[9];
    const float* decbih = (const float*)d_in[10];
    const float* decbhh = (const float*)d_in[11];
    const float* W_reg  = (const float*)d_in[12];
    const float* b_reg  = (const float*)d_in[13];
    float* out = (float*)d_out;

    cudaFuncSetAttribute(rnn_kernel, cudaFuncAttributeMaxDynamicSharedMemorySize, SMEM_BYTES);

    prep_kernel<<<FIN_ + 1, 256>>>(W_emb, b_emb, encWih, encbih, encbhh, decWih);
    emb_gemm<<<dim3(B_ / 128, T_), 256>>>(X);
    rnn_kernel<<<NCTA, RTHREADS, SMEM_BYTES>>>(encWih, encWhh, encbih, encbhh,
                                               decWih, decWhh, decbih, decbhh,
                                               W_reg, b_reg, out);
}

// round 10
// speedup vs baseline: 3.2729x; 1.0201x over previous
#include <cuda_runtime.h>

// Problem constants
#define B_    2048
#define T_    512
#define FIN_  32
#define H_    64
#define G4_   256        // 4*H
#define HOR_  48
#define FOUT_ 8
#define NROW  14         // batch rows per CTA
#define NCTA  147        // ceil(2048/14)
#define RTHREADS 512
#define G0ROW (B_ * G4_)

typedef unsigned long long u64;

// ---------------- scratch (__device__ globals; no cudaMalloc allowed) ----------------
// d_g0 layout: [t][b][unit*4 + gate]  (float4 per hidden unit = {i,f,g,o})
__device__ float d_g0[(size_t)T_ * B_ * G4_];
__device__ float d_WcT[FIN_ * G4_];             // combined (Wih0 @ W_emb), packed-channel order
__device__ float d_bc[G4_];                     // combined layer0 bias, packed-channel order
__device__ float d_wih0P[H_ * G4_];             // decoder Wih[0], woff-packed

// ---------------- fast activations ----------------
__device__ __forceinline__ float sigf(float x) {
    return __fdividef(1.0f, 1.0f + __expf(-x));
}
__device__ __forceinline__ float tanh_f(float x) {
    return __fdividef(2.0f, 1.0f + __expf(-2.0f * x)) - 1.0f;
}

// ---------------- packed fp32x2 helpers ----------------
__device__ __forceinline__ u64 fma2(u64 a, u64 b, u64 c) {
    u64 d;
    asm("fma.rn.f32x2 %0, %1, %2, %3;" : "=l"(d) : "l"(a), "l"(b), "l"(c));
    return d;
}
__device__ __forceinline__ float hadd2(u64 a) {
    float lo, hi;
    asm("mov.b64 {%0, %1}, %2;" : "=f"(lo), "=f"(hi) : "l"(a));
    return lo + hi;
}

// per-row-half named barrier: rh 0 -> id 1 (warps 0-7), rh 1 -> id 2 (warps 8-15)
__device__ __forceinline__ void barh(int rh) {
    asm volatile("bar.sync %0, 256;" :: "r"(rh + 1) : "memory");
}

// packed output-channel index: gate g (0..255) -> unit*4 + gate_slot
__device__ __forceinline__ int pidx(int g) { return ((g & 63) << 2) + (g >> 6); }
// weight packing for W[g][k] within one 256x64 matrix (16384 floats):
// [ks][kq][gate_slot][unit][k&3]
__device__ __forceinline__ int woff(int g, int k) {
    return ((k >> 4) << 12) + (((k >> 2) & 3) << 10) + ((g >> 6) << 8)
         + ((g & 63) << 2) + (k & 3);
}

// ---------------- prep: combined weights / packed transposes ----------------
__global__ void prep_kernel(const float* __restrict__ W_emb, const float* __restrict__ b_emb,
                            const float* __restrict__ encWih, const float* __restrict__ encbih,
                            const float* __restrict__ encbhh, const float* __restrict__ decWih)
{
    int g  = threadIdx.x;   // original gate index 0..255
    int bb = blockIdx.x;    // 0..32
    float wrow[H_];
#pragma unroll
    for (int h = 0; h < H_; h++) wrow[h] = encWih[g * H_ + h];

    if (bb == FIN_) {
        float b = encbih[g] + encbhh[g];
#pragma unroll
        for (int h = 0; h < H_; h++) b = fmaf(wrow[h], b_emb[h], b);
        d_bc[pidx(g)] = b;
#pragma unroll
        for (int k = 0; k < H_; k++)
            d_wih0P[woff(g, k)] = decWih[g * H_ + k];
    } else {
        int f = bb;
        float s = 0.f;
#pragma unroll
        for (int h = 0; h < H_; h++) s = fmaf(wrow[h], W_emb[h * FIN_ + f], s);
        d_WcT[f * G4_ + pidx(g)] = s;
    }
}

// ---------------- GEMM: d_g0[t][b][c] = X[b][t][:] @ WcT[:, c] + bc[c] ----------------
__global__ void __launch_bounds__(256)
emb_gemm(const float* __restrict__ X)
{
    __shared__ float sX[128 * FIN_];
    const int t   = blockIdx.y;
    const int b0  = blockIdx.x * 128;
    const int tid = threadIdx.x;   // packed channel

#pragma unroll
    for (int q = 0; q < 4; q++) {
        int lin = tid + q * 256;
        int rr = lin >> 3, f4 = lin & 7;
        float4 v = *(const float4*)(X + ((size_t)(b0 + rr) * T_ + t) * FIN_ + f4 * 4);
        *(float4*)(sX + rr * FIN_ + f4 * 4) = v;
    }
    float w[FIN_];
#pragma unroll
    for (int f = 0; f < FIN_; f++) w[f] = d_WcT[f * G4_ + tid];
    const float bias = d_bc[tid];
    __syncthreads();

    float* dst = d_g0 + (size_t)t * B_ * G4_ + (size_t)b0 * G4_ + tid;
#pragma unroll 2
    for (int rr = 0; rr < 128; rr++) {
        float a = bias;
        const float* xr = sX + rr * FIN_;
#pragma unroll
        for (int f = 0; f < FIN_; f += 4) {
            float4 x = *(const float4*)(xr + f);
            a = fmaf(x.x, w[f + 0], a);
            a = fmaf(x.y, w[f + 1], a);
            a = fmaf(x.z, w[f + 2], a);
            a = fmaf(x.w, w[f + 3], a);
        }
        dst[(size_t)rr * G4_] = a;
    }
}

// ---------------- matvec: 7 rows x 16 k x 4 gates (i,f,g,o of unit gq) ----------------
// hb = h row base + ks*16 ; wb = matrix base + ks*4096 (smem)
__device__ __forceinline__ void mv4(u64 acc[7][4], const float* __restrict__ hb,
                                    const float* __restrict__ wb, int gq)
{
#pragma unroll
    for (int kq = 0; kq < 4; kq++) {
        const float* wp = wb + kq * 1024 + (gq << 2);
        ulonglong2 wi = *(const ulonglong2*)(wp);
        ulonglong2 wf = *(const ulonglong2*)(wp + 256);
        ulonglong2 wg = *(const ulonglong2*)(wp + 512);
        ulonglong2 wo = *(const ulonglong2*)(wp + 768);
        const float* hq = hb + kq * 4;
#pragma unroll
        for (int r = 0; r < 7; r++) {
            ulonglong2 h = *(const ulonglong2*)(hq + r * 64);
            acc[r][0] = fma2(h.x, wi.x, acc[r][0]);
            acc[r][1] = fma2(h.x, wf.x, acc[r][1]);
            acc[r][2] = fma2(h.x, wg.x, acc[r][2]);
            acc[r][3] = fma2(h.x, wo.x, acc[r][3]);
            acc[r][0] = fma2(h.y, wi.y, acc[r][0]);
            acc[r][1] = fma2(h.y, wf.y, acc[r][1]);
            acc[r][2] = fma2(h.y, wg.y, acc[r][2]);
            acc[r][3] = fma2(h.y, wo.y, acc[r][3]);
        }
    }
}

// same, weights streamed from global (decoder dWih0, L2-resident)
__device__ __forceinline__ void mv4g(u64 acc[7][4], const float* __restrict__ hb,
                                     const float* __restrict__ wb, int gq)
{
#pragma unroll
    for (int kq = 0; kq < 4; kq++) {
        const float* wp = wb + kq * 1024 + (gq << 2);
        ulonglong2 wi = __ldg((const ulonglong2*)(wp));
        ulonglong2 wf = __ldg((const ulonglong2*)(wp + 256));
        ulonglong2 wg = __ldg((const ulonglong2*)(wp + 512));
        ulonglong2 wo = __ldg((const ulonglong2*)(wp + 768));
        const float* hq = hb + kq * 4;
#pragma unroll
        for (int r = 0; r < 7; r++) {
            ulonglong2 h = *(const ulonglong2*)(hq + r * 64);
            acc[r][0] = fma2(h.x, wi.x, acc[r][0]);
            acc[r][1] = fma2(h.x, wf.x, acc[r][1]);
            acc[r][2] = fma2(h.x, wg.x, acc[r][2]);
            acc[r][3] = fma2(h.x, wo.x, acc[r][3]);
            acc[r][0] = fma2(h.y, wi.y, acc[r][0]);
            acc[r][1] = fma2(h.y, wf.y, acc[r][1]);
            acc[r][2] = fma2(h.y, wg.y, acc[r][2]);
            acc[r][3] = fma2(h.y, wo.y, acc[r][3]);
        }
    }
}

__device__ __forceinline__ void store_part(const u64 acc[7][4], float* __restrict__ buf,
                                           int rbase, int gq)
{
#pragma unroll
    for (int r = 0; r < 7; r++) {
        float4 v;
        v.x = hadd2(acc[r][0]); v.y = hadd2(acc[r][1]);
        v.z = hadd2(acc[r][2]); v.w = hadd2(acc[r][3]);
        *(float4*)(buf + (rbase + r) * G4_ + (gq << 2)) = v;
    }
}

__device__ __forceinline__ void add_part(const u64 acc[7][4], float* __restrict__ buf,
                                         int rbase, int gq)
{
#pragma unroll
    for (int r = 0; r < 7; r++) {
        float* p = buf + (rbase + r) * G4_ + (gq << 2);
        float4 v = *(const float4*)(p);
        v.x += hadd2(acc[r][0]); v.y += hadd2(acc[r][1]);
        v.z += hadd2(acc[r][2]); v.w += hadd2(acc[r][3]);
        *(float4*)(p) = v;
    }
}

// pointwise LSTM for one element; gates in float4 {i,f,g,o}; c in register
__device__ __forceinline__ void lstm_e(float4 g4, float& c, float* __restrict__ hout)
{
    float cn = sigf(g4.y) * c + sigf(g4.x) * tanh_f(g4.z);
    c = cn;
    *hout = sigf(g4.w) * tanh_f(cn);
}

__device__ __forceinline__ float4 sum3(float4 a, float4 b, float4 d)
{
    float4 v;
    v.x = a.x + b.x + d.x; v.y = a.y + b.y + d.y;
    v.z = a.z + b.z + d.z; v.w = a.w + b.w + d.w;
    return v;
}

// smem: sW 3*16384 | sH 2*896 | sP0 3584 | sP1 3584  = 58112 floats = 232448 B (227 KB)
#define SMEM_FLOATS (3*16384 + 2*896 + 3584 + 3584)
#define SMEM_BYTES  (SMEM_FLOATS * 4)

__global__ void __launch_bounds__(RTHREADS, 1)
rnn_kernel(const float* __restrict__ encWih, const float* __restrict__ encWhh,
           const float* __restrict__ encbih, const float* __restrict__ encbhh,
           const float* __restrict__ decWih, const float* __restrict__ decWhh,
           const float* __restrict__ decbih, const float* __restrict__ decbhh,
           const float* __restrict__ Wreg,   const float* __restrict__ breg,
           float* __restrict__ out)
{
    extern __shared__ float sm[];
    float* sW  = sm;                 // 3 matrices, woff-packed
    float* sH  = sW + 49152;         // [layer][14][64]
    float* sP0 = sH + 1792;          // partial/final gate buffer A [14][256]
    float* sP1 = sP0 + 3584;         // partial/final gate buffer B [14][256]

    const int tid   = threadIdx.x;
    const int gq    = tid & 63;            // hidden unit
    const int ks    = (tid >> 6) & 3;      // k-split (k in [16ks, 16ks+16))
    const int rh    = tid >> 8;            // row-half
    const int rbase = rh * 7;
    const int lt    = tid & 255;           // lane within row-half
    const int b0    = blockIdx.x * NROW;

    float* myBuf = (ks < 2) ? sP0 : sP1;
    const bool addL0 = ((ks & 1) == 0);    // L0: ks0,ks2 add; ks1,ks3 store
    // L1: roles swap: ks0,ks2 store; ks1,ks3 add

    // pack encoder weights: slot0=encWhh[0], slot1=encWih[1], slot2=encWhh[1]
    for (int i = tid; i < 16384; i += RTHREADS) {
        int g = i >> 6, k = i & 63;
        int dst = woff(g, k);
        sW[dst]         = encWhh[i];
        sW[16384 + dst] = encWih[16384 + i];
        sW[32768 + dst] = encWhh[16384 + i];
    }
    for (int i = tid; i < 2 * 896; i += RTHREADS) sH[i] = 0.f;
    __syncthreads();

    // update-phase element mapping (per rh: 448 elems over 256 threads)
    const int e0 = lt, e1 = lt + 256;
    const bool has_e1 = (lt < 192);
    const int r0 = e0 >> 6, j0 = e0 & 63;
    const int r1 = e1 >> 6, j1 = e1 & 63;
    const int eoff0 = (rbase + r0) * G4_ + (j0 << 2);
    const int eoff1 = (rbase + r1) * G4_ + (j1 << 2);
    float* h0p0 = sH + (rbase + r0) * 64 + j0;
    float* h0p1 = sH + (rbase + r1) * 64 + j1;
    float* h1p0 = h0p0 + 896;
    float* h1p1 = h0p1 + 896;

    // encoder L1 bias per element (registers)
    float4 b1a, b1b;
    b1a.x = encbih[256 + j0]       + encbhh[256 + j0];
    b1a.y = encbih[256 + 64 + j0]  + encbhh[256 + 64 + j0];
    b1a.z = encbih[256 + 128 + j0] + encbhh[256 + 128 + j0];
    b1a.w = encbih[256 + 192 + j0] + encbhh[256 + 192 + j0];
    b1b.x = encbih[256 + j1]       + encbhh[256 + j1];
    b1b.y = encbih[256 + 64 + j1]  + encbhh[256 + 64 + j1];
    b1b.z = encbih[256 + 128 + j1] + encbhh[256 + 128 + j1];
    b1b.w = encbih[256 + 192 + j1] + encbhh[256 + 192 + j1];

    // x-part gmem offsets for update elements (clamped for tail CTA)
    int bcl0 = b0 + rbase + r0; if (bcl0 >= B_) bcl0 = B_ - 1;
    int bcl1 = b0 + rbase + r1; if (bcl1 >= B_) bcl1 = B_ - 1;
    const size_t gxo0 = (size_t)bcl0 * G4_ + (j0 << 2);
    const size_t gxo1 = (size_t)bcl1 * G4_ + (j1 << 2);

    float4 gx0 = *(const float4*)(d_g0 + gxo0);
    float4 gx1 = *(const float4*)(d_g0 + gxo1);

    const float* hb0 = sH + rbase * 64 + ks * 16;
    const float* hb1 = hb0 + 896;
    float c0a = 0.f, c0b = 0.f, c1a = 0.f, c1b = 0.f;

    // -------------------- encoder: 512 steps --------------------
    for (int t = 0; t < T_; t++) {
        u64 acc[7][4];
        // ---- layer 0: Whh0 x h0 ----
#pragma unroll
        for (int r = 0; r < 7; r++) { acc[r][0] = acc[r][1] = acc[r][2] = acc[r][3] = 0ull; }
        mv4(acc, hb0, sW + ks * 4096, gq);
        if (!addL0) store_part(acc, myBuf, rbase, gq);
        barh(rh);
        if (addL0) add_part(acc, myBuf, rbase, gq);
        barh(rh);
        // update L0: gates = sP0 + sP1 + x-part
        {
            float4 p = *(const float4*)(sP0 + eoff0);
            float4 q = *(const float4*)(sP1 + eoff0);
            lstm_e(sum3(p, q, gx0), c0a, h0p0);
            if (has_e1) {
                float4 p2 = *(const float4*)(sP0 + eoff1);
                float4 q2 = *(const float4*)(sP1 + eoff1);
                lstm_e(sum3(p2, q2, gx1), c0b, h0p1);
            }
            if (t + 1 < T_) {   // prefetch next step's x-part
                const float* pn = d_g0 + (size_t)(t + 1) * G0ROW;
                gx0 = *(const float4*)(pn + gxo0);
                gx1 = *(const float4*)(pn + gxo1);
            }
        }
        barh(rh);
        // ---- layer 1: Wih1 x h0_new + Whh1 x h1 ----
#pragma unroll
        for (int r = 0; r < 7; r++) { acc[r][0] = acc[r][1] = acc[r][2] = acc[r][3] = 0ull; }
        mv4(acc, hb0, sW + 16384 + ks * 4096, gq);
        mv4(acc, hb1, sW + 32768 + ks * 4096, gq);
        if (addL0) store_part(acc, myBuf, rbase, gq);   // roles swapped
        barh(rh);
        if (!addL0) add_part(acc, myBuf, rbase, gq);
        barh(rh);
        // update L1: gates = sP0 + sP1 + bias
        {
            float4 p = *(const float4*)(sP0 + eoff0);
            float4 q = *(const float4*)(sP1 + eoff0);
            lstm_e(sum3(p, q, b1a), c1a, h1p0);
            if (has_e1) {
                float4 p2 = *(const float4*)(sP0 + eoff1);
                float4 q2 = *(const float4*)(sP1 + eoff1);
                lstm_e(sum3(p2, q2, b1b), c1b, h1p1);
            }
        }
        barh(rh);
    }

    // -------------------- decoder setup (sW shared across rh: full syncs) --------------------
    __syncthreads();
    for (int i = tid; i < 16384; i += RTHREADS) {
        int g = i >> 6, k = i & 63;
        int dst = woff(g, k);
        sW[dst]         = decWhh[i];             // dWhh0
        sW[16384 + dst] = decWih[16384 + i];     // dWih1
        sW[32768 + dst] = decWhh[16384 + i];     // dWhh1
    }
    // decoder biases per element (registers)
    float4 db0a, db0b, db1a, db1b;
    db0a.x = decbih[j0]       + decbhh[j0];
    db0a.y = decbih[64 + j0]  + decbhh[64 + j0];
    db0a.z = decbih[128 + j0] + decbhh[128 + j0];
    db0a.w = decbih[192 + j0] + decbhh[192 + j0];
    db0b.x = decbih[j1]       + decbhh[j1];
    db0b.y = decbih[64 + j1]  + decbhh[64 + j1];
    db0b.z = decbih[128 + j1] + decbhh[128 + j1];
    db0b.w = decbih[192 + j1] + decbhh[192 + j1];
    db1a.x = decbih[256 + j0]       + decbhh[256 + j0];
    db1a.y = decbih[256 + 64 + j0]  + decbhh[256 + 64 + j0];
    db1a.z = decbih[256 + 128 + j0] + decbhh[256 + 128 + j0];
    db1a.w = decbih[256 + 192 + j0] + decbhh[256 + 192 + j0];
    db1b.x = decbih[256 + j1]       + decbhh[256 + j1];
    db1b.y = decbih[256 + 64 + j1]  + decbhh[256 + 64 + j1];
    db1b.z = decbih[256 + 128 + j1] + decbhh[256 + 128 + j1];
    db1b.w = decbih[256 + 192 + j1] + decbhh[256 + 192 + j1];
    c0a = c0b = c1a = c1b = 0.f;                 // c reset; h carries over
    __syncthreads();

    // -------------------- decoder: 48 steps --------------------
    for (int t = 0; t < HOR_; t++) {
        u64 acc[7][4];
        // ---- layer 0: dWih0 x h1_prev (gmem weights) + dWhh0 x h0 ----
#pragma unroll
        for (int r = 0; r < 7; r++) { acc[r][0] = acc[r][1] = acc[r][2] = acc[r][3] = 0ull; }
        mv4g(acc, hb1, d_wih0P + ks * 4096, gq);
        mv4 (acc, hb0, sW + ks * 4096, gq);
        if (!addL0) store_part(acc, myBuf, rbase, gq);
        barh(rh);
        if (addL0) add_part(acc, myBuf, rbase, gq);
        barh(rh);
        {
            float4 p = *(const float4*)(sP0 + eoff0);
            float4 q = *(const float4*)(sP1 + eoff0);
            lstm_e(sum3(p, q, db0a), c0a, h0p0);
            if (has_e1) {
                float4 p2 = *(const float4*)(sP0 + eoff1);
                float4 q2 = *(const float4*)(sP1 + eoff1);
                lstm_e(sum3(p2, q2, db0b), c0b, h0p1);
            }
        }
        barh(rh);
        // ---- layer 1 ----
#pragma unroll
        for (int r = 0; r < 7; r++) { acc[r][0] = acc[r][1] = acc[r][2] = acc[r][3] = 0ull; }
        mv4(acc, hb0, sW + 16384 + ks * 4096, gq);
        mv4(acc, hb1, sW + 32768 + ks * 4096, gq);
        if (addL0) store_part(acc, myBuf, rbase, gq);
        barh(rh);
        if (!addL0) add_part(acc, myBuf, rbase, gq);
        barh(rh);
        {
            float4 p = *(const float4*)(sP0 + eoff0);
            float4 q = *(const float4*)(sP1 + eoff0);
            lstm_e(sum3(p, q, db1a), c1a, h1p0);
            if (has_e1) {
                float4 p2 = *(const float4*)(sP0 + eoff1);
                float4 q2 = *(const float4*)(sP1 + eoff1);
                lstm_e(sum3(p2, q2, db1b), c1b, h1p1);
            }
        }
        barh(rh);
        // regression head: y = h1_new @ Wreg^T + breg (Wreg from global, L2-resident)
        if (lt < 7 * FOUT_) {
            int rloc = lt >> 3, o = lt & 7;
            int b = b0 + rbase + rloc;
            if (b < B_) {
                float a = __ldg(&breg[o]);
                const float* hr = sH + 896 + (rbase + rloc) * 64;
#pragma unroll
                for (int k = 0; k < H_; k += 4) {
                    float4 h4 = *(const float4*)(hr + k);
                    float4 w4 = __ldg((const float4*)(Wreg + o * H_ + k));
                    a = fmaf(h4.x, w4.x, a);
                    a = fmaf(h4.y, w4.y, a);
                    a = fmaf(h4.z, w4.z, a);
                    a = fmaf(h4.w, w4.w, a);
                }
                out[((size_t)b * HOR_ + t) * FOUT_ + o] = a;
            }
        }
    }
}

// ---------------- launch ----------------
extern "C" void kernel_launch(void* const* d_in, const int* in_sizes, int n_in,
                              void* d_out, int out_size)
{
    const float* X      = (const float*)d_in[0];
    // d_in[1] = X_mask : all-ones, unused by reference
    const float* W_emb  = (const float*)d_in[2];
    const float* b_emb  = (const float*)d_in[3];
    const float* encWih = (const float*)d_in[4];
    const float* encWhh = (const float*)d_in[5];
    const float* encbih = (const float*)d_in[6];
    const float* encbhh = (const float*)d_in[7];
    const float* decWih = (const float*)d_in[8];
    const float* decWhh = (const float*)d_in[9];
    const float* decbih = (const float*)d_in[10];
    const float* decbhh = (const float*)d_in[11];
    const float* W_reg  = (const float*)d_in[12];
    const float* b_reg  = (const float*)d_in[13];
    float* out = (float*)d_out;

    cudaFuncSetAttribute(rnn_kernel, cudaFuncAttributeMaxDynamicSharedMemorySize, SMEM_BYTES);

    prep_kernel<<<FIN_ + 1, 256>>>(W_emb, b_emb, encWih, encbih, encbhh, decWih);
    emb_gemm<<<dim3(B_ / 128, T_), 256>>>(X);
    rnn_kernel<<<NCTA, RTHREADS, SMEM_BYTES>>>(encWih, encWhh, encbih, encbhh,
                                               decWih, decWhh, decbih, decbhh,
                                               W_reg, b_reg, out);
}